// round 3
// baseline (speedup 1.0000x reference)
#include <cuda_runtime.h>
#include <cuda_bf16.h>
#include <math.h>
#include <stdint.h>

// Problem constants
#define BB 2
#define SS 2048
#define DD 1024
#define HH 16
#define MTOT (BB*SS)          // 4096 rows

// ---------------------------------------------------------------------------
// Scratch (device globals; no allocation allowed)
// ---------------------------------------------------------------------------
__device__ __align__(256) __nv_bfloat16 g_WqTh[1024*1024];
__device__ __align__(256) __nv_bfloat16 g_WqTl[1024*1024];
__device__ __align__(256) __nv_bfloat16 g_WkTh[1024*1024];
__device__ __align__(256) __nv_bfloat16 g_WkTl[1024*1024];
__device__ __align__(256) __nv_bfloat16 g_WvTh[1024*1024];
__device__ __align__(256) __nv_bfloat16 g_WvTl[1024*1024];
__device__ __align__(256) __nv_bfloat16 g_WcTh[1024*1024];
__device__ __align__(256) __nv_bfloat16 g_WcTl[1024*1024];
__device__ __align__(256) __nv_bfloat16 g_W1Th[512*1024];
__device__ __align__(256) __nv_bfloat16 g_W1Tl[512*1024];
__device__ __align__(256) __nv_bfloat16 g_W2Th[1024*512];
__device__ __align__(256) __nv_bfloat16 g_W2Tl[1024*512];

__device__ __align__(256) __nv_bfloat16 g_AQh[MTOT*1024];
__device__ __align__(256) __nv_bfloat16 g_AQl[MTOT*1024];
__device__ __align__(256) __nv_bfloat16 g_AKh[MTOT*1024];
__device__ __align__(256) __nv_bfloat16 g_AKl[MTOT*1024];
__device__ __align__(256) __nv_bfloat16 g_AVh[MTOT*1024];
__device__ __align__(256) __nv_bfloat16 g_AVl[MTOT*1024];

__device__ __align__(256) __nv_bfloat16 g_Qh[BB*HH*SS*64];
__device__ __align__(256) __nv_bfloat16 g_Ql[BB*HH*SS*64];
__device__ __align__(256) __nv_bfloat16 g_Kh[BB*HH*SS*64];
__device__ __align__(256) __nv_bfloat16 g_Kl[BB*HH*SS*64];
__device__ __align__(256) float        g_Vf[MTOT*1024];
__device__ __align__(256) __nv_bfloat16 g_Vh[BB*HH*64*SS];
__device__ __align__(256) __nv_bfloat16 g_Vl[BB*HH*64*SS];

__device__ __align__(256) __nv_bfloat16 g_Oh[MTOT*1024];
__device__ __align__(256) __nv_bfloat16 g_Ol[MTOT*1024];
__device__ __align__(256) float        g_T[MTOT*1024];
__device__ __align__(256) float        g_R[MTOT*1024];
__device__ __align__(256) __nv_bfloat16 g_Rh[MTOT*1024];
__device__ __align__(256) __nv_bfloat16 g_Rl[MTOT*1024];
__device__ __align__(256) __nv_bfloat16 g_Hh[MTOT*512];
__device__ __align__(256) __nv_bfloat16 g_Hl[MTOT*512];

// ---------------------------------------------------------------------------
// Helpers
// ---------------------------------------------------------------------------
#define CP16(dst,src) asm volatile("cp.async.cg.shared.global [%0], [%1], 16;\n" :: "r"(dst), "l"(src))
#define CP_COMMIT()   asm volatile("cp.async.commit_group;\n")
#define CP_WAIT(n)    asm volatile("cp.async.wait_group %0;\n" :: "n"(n))

// swizzled byte offsets into bf16 tiles
// 32-wide (64B rows): chunk xor (row>>1)&3
#define OFF32(row,k) (((row)<<6) + ((((k)>>3) ^ (((row)>>1)&3))<<4) + (((k)&7)<<1))
// 64-wide (128B rows): chunk xor row&7
#define OFF64(row,k) (((row)<<7) + ((((k)>>3) ^ ((row)&7))<<4) + (((k)&7)<<1))

__device__ __forceinline__ uint32_t smaddr(const void* p){
    return (uint32_t)__cvta_generic_to_shared(p);
}

__device__ __forceinline__ void mma_bf16(float* c, const uint32_t* a, uint32_t b0, uint32_t b1){
    asm volatile("mma.sync.aligned.m16n8k16.row.col.f32.bf16.bf16.f32 "
        "{%0,%1,%2,%3},{%4,%5,%6,%7},{%8,%9},{%0,%1,%2,%3};\n"
        : "+f"(c[0]),"+f"(c[1]),"+f"(c[2]),"+f"(c[3])
        : "r"(a[0]),"r"(a[1]),"r"(a[2]),"r"(a[3]),"r"(b0),"r"(b1));
}

__device__ __forceinline__ void ldmx4(uint32_t* d, uint32_t addr){
    asm volatile("ldmatrix.sync.aligned.m8n8.x4.shared.b16 {%0,%1,%2,%3}, [%4];\n"
        : "=r"(d[0]),"=r"(d[1]),"=r"(d[2]),"=r"(d[3]) : "r"(addr));
}

__device__ __forceinline__ uint32_t packbf(float x, float y){
    __nv_bfloat162 t = __floats2bfloat162_rn(x, y);
    return *reinterpret_cast<uint32_t*>(&t);
}

__device__ __forceinline__ void split2(float x, __nv_bfloat16& h, __nv_bfloat16& l){
    h = __float2bfloat16_rn(x);
    l = __float2bfloat16_rn(x - __bfloat162float(h));
}

__device__ __forceinline__ void split_pack(float x, float y, uint32_t& hp, uint32_t& lp){
    __nv_bfloat162 hh = __floats2bfloat162_rn(x, y);
    hp = *reinterpret_cast<uint32_t*>(&hh);
    __nv_bfloat162 ll = __floats2bfloat162_rn(x - __bfloat162float(hh.x),
                                              y - __bfloat162float(hh.y));
    lp = *reinterpret_cast<uint32_t*>(&ll);
}

// ---------------------------------------------------------------------------
// Weight transpose + split: in [K][N] fp32 -> outh/outl [N][K] bf16
// grid (N/32, K/32), block (32, 8)
// ---------------------------------------------------------------------------
__global__ void transpose_split(const float* __restrict__ in,
                                __nv_bfloat16* __restrict__ outh,
                                __nv_bfloat16* __restrict__ outl, int K, int N)
{
    __shared__ float t[32][33];
    const int n0 = blockIdx.x*32, k0 = blockIdx.y*32;
    const int tx = threadIdx.x, ty = threadIdx.y;
    #pragma unroll
    for (int r = 0; r < 4; r++)
        t[ty + r*8][tx] = in[(size_t)(k0 + ty + r*8)*N + n0 + tx];
    __syncthreads();
    #pragma unroll
    for (int r = 0; r < 4; r++){
        int nl = ty + r*8;
        float v = t[tx][nl];
        __nv_bfloat16 h, l; split2(v, h, l);
        size_t o = (size_t)(n0 + nl)*K + k0 + tx;
        outh[o] = h; outl[o] = l;
    }
}

// ---------------------------------------------------------------------------
// Plain split: in [n] fp32 -> h/l bf16 (vectorized by 4)
// ---------------------------------------------------------------------------
__global__ void split_plain(const float* __restrict__ in,
                            __nv_bfloat16* __restrict__ oh,
                            __nv_bfloat16* __restrict__ ol, int n4)
{
    int i = blockIdx.x*256 + threadIdx.x;
    if (i >= n4) return;
    float4 v = ((const float4*)in)[i];
    uint2 hh, ll;
    split_pack(v.x, v.y, hh.x, ll.x);
    split_pack(v.z, v.w, hh.y, ll.y);
    ((uint2*)oh)[i] = hh;
    ((uint2*)ol)[i] = ll;
}

// ---------------------------------------------------------------------------
// V transpose + split: Vf [M][1024] -> Vh/Vl [B*H][64][S]
// grid (S/32, 2, B*H), block (32,8)
// ---------------------------------------------------------------------------
__global__ void v_transpose_split(const float* __restrict__ Vf,
                                  __nv_bfloat16* __restrict__ Vh,
                                  __nv_bfloat16* __restrict__ Vl)
{
    __shared__ float t[32][33];
    const int bh = blockIdx.z;
    const int s0 = blockIdx.x*32, d0 = blockIdx.y*32;
    const int b = bh >> 4, h = bh & 15;
    const int tx = threadIdx.x, ty = threadIdx.y;
    #pragma unroll
    for (int r = 0; r < 4; r++)
        t[ty + r*8][tx] = Vf[(size_t)(b*SS + s0 + ty + r*8)*1024 + h*64 + d0 + tx];
    __syncthreads();
    #pragma unroll
    for (int r = 0; r < 4; r++){
        int dl = ty + r*8;
        float v = t[tx][dl];
        __nv_bfloat16 hh, ll; split2(v, hh, ll);
        size_t o = ((size_t)bh*64 + d0 + dl)*SS + s0 + tx;
        Vh[o] = hh; Vl[o] = ll;
    }
}

// ---------------------------------------------------------------------------
// Split-bf16 TN GEMM: acc = A[M,K] @ B^T[N,K] + bias
// MODE 0: C fp32 [M][N]
// MODE 1: (acc+bias)*scale -> split bf16 to Dh/Dl in [bh][s][64] layout
// MODE 2: relu(acc+bias) -> split bf16 to Dh/Dl [M][N]
// 128x128x32 tiles, 256 threads (8 warps 2x4), ldmatrix, 3-stage cp.async.
// ---------------------------------------------------------------------------
#define G_STAGE 32768

template<int MODE>
__global__ __launch_bounds__(256, 2) void gemm_split(
    const __nv_bfloat16* __restrict__ Ah, const __nv_bfloat16* __restrict__ Al,
    const __nv_bfloat16* __restrict__ Bh, const __nv_bfloat16* __restrict__ Bl,
    const float* __restrict__ bias, float* __restrict__ C,
    __nv_bfloat16* __restrict__ Dh, __nv_bfloat16* __restrict__ Dl,
    float scale, int M, int N, int K)
{
    extern __shared__ char sm[];
    const int tid = threadIdx.x;
    const int wid = tid >> 5, lane = tid & 31;
    const int wm = wid >> 2, wn = wid & 3;
    const int r = lane >> 2, q = lane & 3;
    const int lrow = lane & 15, lsel = lane >> 4;
    const int rowBase = blockIdx.y*128, colBase = blockIdx.x*128;

    // cp.async mapping: row = tid>>1, chunks {2*(tid&1), 2*(tid&1)+1}
    const int ldRow = tid >> 1;
    const int c0 = (tid & 1)*2;
    const int sw = (ldRow >> 1) & 3;
    const int rowoff = ldRow << 6;
    const uint32_t d0 = rowoff + (((c0  ) ^ sw) << 4);
    const uint32_t d1 = rowoff + (((c0+1) ^ sw) << 4);

    const __nv_bfloat16* srcs[4];
    srcs[0] = Ah + (size_t)(rowBase + ldRow)*K;
    srcs[1] = Al + (size_t)(rowBase + ldRow)*K;
    srcs[2] = Bh + (size_t)(colBase + ldRow)*K;
    srcs[3] = Bl + (size_t)(colBase + ldRow)*K;

    const uint32_t smbase = smaddr(sm);

    float acc[4][4][4];
    #pragma unroll
    for (int i=0;i<4;i++)
        #pragma unroll
        for (int j=0;j<4;j++)
            #pragma unroll
            for (int k=0;k<4;k++) acc[i][j][k] = 0.0f;

    const int KT = K >> 5;

    #define G_ISSUE(st, k0) { \
        uint32_t sb_ = smbase + (st)*G_STAGE; \
        _Pragma("unroll") \
        for (int p = 0; p < 4; p++){ \
            const __nv_bfloat16* s_ = srcs[p] + (k0) + c0*8; \
            CP16(sb_ + p*8192 + d0, s_); \
            CP16(sb_ + p*8192 + d1, s_ + 8); \
        } }

    G_ISSUE(0, 0);  CP_COMMIT();
    G_ISSUE(1, 32); CP_COMMIT();
    G_ISSUE(2, 64); CP_COMMIT();
    CP_WAIT(2); __syncthreads();

    for (int kt = 0; kt < KT; kt++){
        const int slot = kt % 3;
        const uint32_t sb = smbase + slot*G_STAGE;
        #pragma unroll
        for (int ks = 0; ks < 2; ks++){
            const int kk = (2*ks + lsel)*8;
            uint32_t bh[2][4], bl[2][4];
            #pragma unroll
            for (int ntp = 0; ntp < 2; ntp++){
                uint32_t off = OFF32(wn*32 + ntp*16 + lrow, kk);
                ldmx4(bh[ntp], sb + 16384 + off);
                ldmx4(bl[ntp], sb + 24576 + off);
            }
            #pragma unroll
            for (int mt = 0; mt < 4; mt++){
                uint32_t off = OFF32(wm*64 + mt*16 + lrow, kk);
                uint32_t ah[4], al[4];
                ldmx4(ah, sb + off);
                ldmx4(al, sb + 8192 + off);
                #pragma unroll
                for (int ntp = 0; ntp < 2; ntp++)
                    #pragma unroll
                    for (int sub = 0; sub < 2; sub++){
                        int nt = ntp*2 + sub;
                        mma_bf16(acc[mt][nt], ah, bh[ntp][sub], bh[ntp][2+sub]);
                        mma_bf16(acc[mt][nt], ah, bl[ntp][sub], bl[ntp][2+sub]);
                        mma_bf16(acc[mt][nt], al, bh[ntp][sub], bh[ntp][2+sub]);
                    }
            }
        }
        __syncthreads();
        if (kt + 3 < KT){ G_ISSUE(slot, (kt+3)*32); }
        CP_COMMIT();
        CP_WAIT(2);
        __syncthreads();
    }
    #undef G_ISSUE

    // Epilogue
    #pragma unroll
    for (int mt = 0; mt < 4; mt++){
        int row0 = rowBase + wm*64 + mt*16 + r;
        int row1 = row0 + 8;
        #pragma unroll
        for (int nt = 0; nt < 4; nt++){
            int col = colBase + wn*32 + nt*8 + q*2;
            float b0 = bias[col], b1 = bias[col+1];
            float v0 = acc[mt][nt][0] + b0, v1 = acc[mt][nt][1] + b1;
            float v2 = acc[mt][nt][2] + b0, v3 = acc[mt][nt][3] + b1;
            if (MODE == 0){
                float2 p0 = {v0, v1}, p1 = {v2, v3};
                *(float2*)(C + (size_t)row0*N + col) = p0;
                *(float2*)(C + (size_t)row1*N + col) = p1;
            } else if (MODE == 1){
                v0 *= scale; v1 *= scale; v2 *= scale; v3 *= scale;
                int h = col >> 6, dd = col & 63;
                size_t o0 = (((size_t)(row0>>11)*16 + h)*2048 + (row0 & 2047))*64 + dd;
                size_t o1 = (((size_t)(row1>>11)*16 + h)*2048 + (row1 & 2047))*64 + dd;
                uint32_t hp, lp;
                split_pack(v0, v1, hp, lp);
                *(uint32_t*)(Dh + o0) = hp; *(uint32_t*)(Dl + o0) = lp;
                split_pack(v2, v3, hp, lp);
                *(uint32_t*)(Dh + o1) = hp; *(uint32_t*)(Dl + o1) = lp;
            } else {
                v0 = fmaxf(v0, 0.f); v1 = fmaxf(v1, 0.f);
                v2 = fmaxf(v2, 0.f); v3 = fmaxf(v3, 0.f);
                uint32_t hp, lp;
                split_pack(v0, v1, hp, lp);
                *(uint32_t*)(Dh + (size_t)row0*N + col) = hp;
                *(uint32_t*)(Dl + (size_t)row0*N + col) = lp;
                split_pack(v2, v3, hp, lp);
                *(uint32_t*)(Dh + (size_t)row1*N + col) = hp;
                *(uint32_t*)(Dl + (size_t)row1*N + col) = lp;
            }
        }
    }
}

// ---------------------------------------------------------------------------
// Flash attention, split-bf16 mma + ldmatrix. Grid (S/64, H, B), 128 threads.
// Q/K layout [B*H][S][64]; V layout [B*H][64][S]; out split bf16 [M][1024].
// ---------------------------------------------------------------------------
#define A_STAGE 33024        // Kh 8K | Kl 8K | Vh 8K | Vl 8K | mask 256B
#define A_SMEM  (2*A_STAGE + 16384)

__global__ __launch_bounds__(128) void attn_mma(
    const __nv_bfloat16* __restrict__ Qh, const __nv_bfloat16* __restrict__ Ql,
    const __nv_bfloat16* __restrict__ Kh, const __nv_bfloat16* __restrict__ Kl,
    const __nv_bfloat16* __restrict__ Vh, const __nv_bfloat16* __restrict__ Vl,
    const float* __restrict__ mask,
    __nv_bfloat16* __restrict__ Oh, __nv_bfloat16* __restrict__ Ol)
{
    extern __shared__ char sm[];
    const int tid = threadIdx.x;
    const int wid = tid >> 5, lane = tid & 31;
    const int r = lane >> 2, q = lane & 3;
    const int lrow = lane & 15, lsel = lane >> 4;
    const int b = blockIdx.z, h = blockIdx.y;
    const int bh = b*HH + h;
    const int q0 = blockIdx.x*64;

    const uint32_t smbase = smaddr(sm);
    const uint32_t QH_OFF = 2*A_STAGE, QL_OFF = 2*A_STAGE + 8192;

    const int ldRow = tid >> 1;
    const int cb = (tid & 1)*4;

    const __nv_bfloat16* kh_g = Kh + ((size_t)bh*SS)*64;
    const __nv_bfloat16* kl_g = Kl + ((size_t)bh*SS)*64;
    const __nv_bfloat16* vh_g = Vh + ((size_t)bh*64)*SS;
    const __nv_bfloat16* vl_g = Vl + ((size_t)bh*64)*SS;
    const float* mk_g = mask + b*SS;

    #define A_ISSUE(st, k0) { \
        uint32_t sb_ = smbase + (st)*A_STAGE; \
        _Pragma("unroll") \
        for (int c = 0; c < 4; c++){ \
            int ch = cb + c; \
            uint32_t doff = (ldRow<<7) + ((ch ^ (ldRow&7))<<4); \
            CP16(sb_ + doff,         kh_g + (size_t)((k0) + ldRow)*64 + ch*8); \
            CP16(sb_ + 8192 + doff,  kl_g + (size_t)((k0) + ldRow)*64 + ch*8); \
            CP16(sb_ + 16384 + doff, vh_g + (size_t)ldRow*SS + (k0) + ch*8); \
            CP16(sb_ + 24576 + doff, vl_g + (size_t)ldRow*SS + (k0) + ch*8); \
        } \
        if (tid < 16) CP16(sb_ + 32768 + tid*16, mk_g + (k0) + tid*4); }

    // prologue: Q + stage0, then stage1
    {
        const __nv_bfloat16* qh_g = Qh + ((size_t)bh*SS + q0)*64;
        const __nv_bfloat16* ql_g = Ql + ((size_t)bh*SS + q0)*64;
        #pragma unroll
        for (int c = 0; c < 4; c++){
            int ch = cb + c;
            uint32_t doff = (ldRow<<7) + ((ch ^ (ldRow&7))<<4);
            CP16(smbase + QH_OFF + doff, qh_g + (size_t)ldRow*64 + ch*8);
            CP16(smbase + QL_OFF + doff, ql_g + (size_t)ldRow*64 + ch*8);
        }
        A_ISSUE(0, 0); CP_COMMIT();
        A_ISSUE(1, 64); CP_COMMIT();
        CP_WAIT(1); __syncthreads();
    }

    // preload Q fragments via ldmatrix
    uint32_t qfh[4][4], qfl[4][4];
    #pragma unroll
    for (int ks = 0; ks < 4; ks++){
        uint32_t off = OFF64(wid*16 + lrow, (2*ks + lsel)*8);
        ldmx4(qfh[ks], smbase + QH_OFF + off);
        ldmx4(qfl[ks], smbase + QL_OFF + off);
    }

    float o[8][4];
    #pragma unroll
    for (int i=0;i<8;i++){ o[i][0]=0.f; o[i][1]=0.f; o[i][2]=0.f; o[i][3]=0.f; }
    float m0 = -INFINITY, m1 = -INFINITY, l0 = 0.f, l1 = 0.f;

    const int KT = SS/64;
    for (int kt = 0; kt < KT; kt++){
        const uint32_t stg = smbase + (kt & 1)*A_STAGE;
        const float* mk = (const float*)(sm + (kt & 1)*A_STAGE + 32768);

        // ---- S = Q @ K^T ----
        float s[8][4];
        #pragma unroll
        for (int i=0;i<8;i++){ s[i][0]=0.f; s[i][1]=0.f; s[i][2]=0.f; s[i][3]=0.f; }

        #pragma unroll
        for (int ks = 0; ks < 4; ks++){
            const int kk = (2*ks + lsel)*8;
            #pragma unroll
            for (int ntp = 0; ntp < 4; ntp++){
                uint32_t off = OFF64(ntp*16 + lrow, kk);
                uint32_t kbh[4], kbl[4];
                ldmx4(kbh, stg + off);
                ldmx4(kbl, stg + 8192 + off);
                mma_bf16(s[2*ntp],   qfh[ks], kbh[0], kbh[2]);
                mma_bf16(s[2*ntp],   qfh[ks], kbl[0], kbl[2]);
                mma_bf16(s[2*ntp],   qfl[ks], kbh[0], kbh[2]);
                mma_bf16(s[2*ntp+1], qfh[ks], kbh[1], kbh[3]);
                mma_bf16(s[2*ntp+1], qfh[ks], kbl[1], kbl[3]);
                mma_bf16(s[2*ntp+1], qfl[ks], kbh[1], kbh[3]);
            }
        }

        // ---- mask + online softmax ----
        float mx0 = -INFINITY, mx1 = -INFINITY;
        #pragma unroll
        for (int nt = 0; nt < 8; nt++){
            float2 mv = *(const float2*)(mk + nt*8 + q*2);
            float a0 = (mv.x - 1.0f)*1e12f, a1 = (mv.y - 1.0f)*1e12f;
            s[nt][0] += a0; s[nt][1] += a1; s[nt][2] += a0; s[nt][3] += a1;
            mx0 = fmaxf(mx0, fmaxf(s[nt][0], s[nt][1]));
            mx1 = fmaxf(mx1, fmaxf(s[nt][2], s[nt][3]));
        }
        mx0 = fmaxf(mx0, __shfl_xor_sync(0xffffffffu, mx0, 1));
        mx0 = fmaxf(mx0, __shfl_xor_sync(0xffffffffu, mx0, 2));
        mx1 = fmaxf(mx1, __shfl_xor_sync(0xffffffffu, mx1, 1));
        mx1 = fmaxf(mx1, __shfl_xor_sync(0xffffffffu, mx1, 2));
        float mn0 = fmaxf(m0, mx0), mn1 = fmaxf(m1, mx1);
        float cr0 = __expf(m0 - mn0), cr1 = __expf(m1 - mn1);
        m0 = mn0; m1 = mn1;
        float sum0 = 0.f, sum1 = 0.f;
        #pragma unroll
        for (int nt = 0; nt < 8; nt++){
            s[nt][0] = __expf(s[nt][0] - mn0);
            s[nt][1] = __expf(s[nt][1] - mn0);
            s[nt][2] = __expf(s[nt][2] - mn1);
            s[nt][3] = __expf(s[nt][3] - mn1);
            sum0 += s[nt][0] + s[nt][1];
            sum1 += s[nt][2] + s[nt][3];
        }
        sum0 += __shfl_xor_sync(0xffffffffu, sum0, 1);
        sum0 += __shfl_xor_sync(0xffffffffu, sum0, 2);
        sum1 += __shfl_xor_sync(0xffffffffu, sum1, 1);
        sum1 += __shfl_xor_sync(0xffffffffu, sum1, 2);
        l0 = l0*cr0 + sum0; l1 = l1*cr1 + sum1;
        #pragma unroll
        for (int nt = 0; nt < 8; nt++){
            o[nt][0] *= cr0; o[nt][1] *= cr0; o[nt][2] *= cr1; o[nt][3] *= cr1;
        }

        // ---- O += P @ V (P repacked from S fragments in registers) ----
        #pragma unroll
        for (int j = 0; j < 4; j++){
            uint32_t ph[4], pl[4];
            split_pack(s[2*j][0],   s[2*j][1],   ph[0], pl[0]);
            split_pack(s[2*j][2],   s[2*j][3],   ph[1], pl[1]);
            split_pack(s[2*j+1][0], s[2*j+1][1], ph[2], pl[2]);
            split_pack(s[2*j+1][2], s[2*j+1][3], ph[3], pl[3]);
            const int kk = (2*j + lsel)*8;
            #pragma unroll
            for (int ntp = 0; ntp < 4; ntp++){
                uint32_t off = OFF64(ntp*16 + lrow, kk);
                uint32_t vbh[4], vbl[4];
                ldmx4(vbh, stg + 16384 + off);
                ldmx4(vbl, stg + 24576 + off);
                mma_bf16(o[2*ntp],   ph, vbh[0], vbh[2]);
                mma_bf16(o[2*ntp],   ph, vbl[0], vbl[2]);
                mma_bf16(o[2*ntp],   pl, vbh[0], vbh[2]);
                mma_bf16(o[2*ntp+1], ph, vbh[1], vbh[3]);
                mma_bf16(o[2*ntp+1], ph, vbl[1], vbl[3]);
                mma_bf16(o[2*ntp+1], pl, vbh[1], vbh[3]);
            }
        }

        __syncthreads();
        if (kt + 2 < KT){
            A_ISSUE(kt & 1, (kt+2)*64); CP_COMMIT(); CP_WAIT(1);
        } else {
            CP_WAIT(0);
        }
        __syncthreads();
    }
    #undef A_ISSUE

    // ---- write O (split bf16) ----
    float inv0 = 1.0f/l0, inv1 = 1.0f/l1;
    int mrow = q0 + wid*16 + r;
    size_t base0 = ((size_t)(b*SS) + mrow)*DD + h*64;
    size_t base1 = base0 + (size_t)8*DD;
    #pragma unroll
    for (int nt = 0; nt < 8; nt++){
        int col = nt*8 + q*2;
        uint32_t hp, lp;
        split_pack(o[nt][0]*inv0, o[nt][1]*inv0, hp, lp);
        *(uint32_t*)(Oh + base0 + col) = hp;
        *(uint32_t*)(Ol + base0 + col) = lp;
        split_pack(o[nt][2]*inv1, o[nt][3]*inv1, hp, lp);
        *(uint32_t*)(Oh + base1 + col) = hp;
        *(uint32_t*)(Ol + base1 + col) = lp;
    }
}

// ---------------------------------------------------------------------------
// Residual add + RMSNorm. SPLIT variant also emits bf16 hi/lo planes.
// ---------------------------------------------------------------------------
template<int SPLIT>
__global__ __launch_bounds__(256) void add_rmsnorm(
    const float* __restrict__ a, const float* __restrict__ b,
    const float* __restrict__ gamma, float* __restrict__ out,
    __nv_bfloat16* __restrict__ oh, __nv_bfloat16* __restrict__ ol)
{
    const int row = blockIdx.x;
    const int t = threadIdx.x;
    const float4* pa = (const float4*)(a + (size_t)row * DD);
    const float4* pb = (const float4*)(b + (size_t)row * DD);
    float4 xa = pa[t], xb = pb[t];
    float4 x;
    x.x = xa.x + xb.x; x.y = xa.y + xb.y; x.z = xa.z + xb.z; x.w = xa.w + xb.w;
    float ss = x.x*x.x + x.y*x.y + x.z*x.z + x.w*x.w;
    #pragma unroll
    for (int o = 16; o >= 1; o >>= 1)
        ss += __shfl_xor_sync(0xffffffffu, ss, o);
    __shared__ float red[8];
    if ((t & 31) == 0) red[t >> 5] = ss;
    __syncthreads();
    float tot = red[0]+red[1]+red[2]+red[3]+red[4]+red[5]+red[6]+red[7];
    float rms = sqrtf(tot * (1.0f / 1024.0f));
    float inv = 1.0f / (rms + 1e-8f);
    float4 gv = ((const float4*)gamma)[t];
    float4 o;
    o.x = gv.x*x.x*inv; o.y = gv.y*x.y*inv; o.z = gv.z*x.z*inv; o.w = gv.w*x.w*inv;
    ((float4*)(out + (size_t)row * DD))[t] = o;
    if (SPLIT){
        uint2 hh, ll;
        split_pack(o.x, o.y, hh.x, ll.x);
        split_pack(o.z, o.w, hh.y, ll.y);
        ((uint2*)(oh + (size_t)row * DD))[t] = hh;
        ((uint2*)(ol + (size_t)row * DD))[t] = ll;
    }
}

// ---------------------------------------------------------------------------
// Launch
// ---------------------------------------------------------------------------
extern "C" void kernel_launch(void* const* d_in, const int* in_sizes, int n_in,
                              void* d_out, int out_size)
{
    const float* query = (const float*)d_in[0];
    const float* key_  = (const float*)d_in[1];
    const float* value = (const float*)d_in[2];
    const float* mask  = (const float*)d_in[3];
    const float* Wq = (const float*)d_in[4];
    const float* bq = (const float*)d_in[5];
    const float* Wk = (const float*)d_in[6];
    const float* bk = (const float*)d_in[7];
    const float* Wv = (const float*)d_in[8];
    const float* bv = (const float*)d_in[9];
    const float* Wc = (const float*)d_in[10];
    const float* bc = (const float*)d_in[11];
    const float* rms1 = (const float*)d_in[12];
    const float* w1 = (const float*)d_in[13];
    const float* b1 = (const float*)d_in[14];
    const float* w2 = (const float*)d_in[15];
    const float* b2 = (const float*)d_in[16];
    const float* rms2 = (const float*)d_in[17];
    float* out = (float*)d_out;

    __nv_bfloat16 *WqTh,*WqTl,*WkTh,*WkTl,*WvTh,*WvTl,*WcTh,*WcTl,*W1Th,*W1Tl,*W2Th,*W2Tl;
    __nv_bfloat16 *AQh,*AQl,*AKh,*AKl,*AVh,*AVl;
    __nv_bfloat16 *Qhp,*Qlp,*Khp,*Klp,*Vhp,*Vlp,*Ohp,*Olp,*Rhp,*Rlp,*Hhp,*Hlp;
    float *Vfp,*Tp,*Rp;
    cudaGetSymbolAddress((void**)&WqTh, g_WqTh); cudaGetSymbolAddress((void**)&WqTl, g_WqTl);
    cudaGetSymbolAddress((void**)&WkTh, g_WkTh); cudaGetSymbolAddress((void**)&WkTl, g_WkTl);
    cudaGetSymbolAddress((void**)&WvTh, g_WvTh); cudaGetSymbolAddress((void**)&WvTl, g_WvTl);
    cudaGetSymbolAddress((void**)&WcTh, g_WcTh); cudaGetSymbolAddress((void**)&WcTl, g_WcTl);
    cudaGetSymbolAddress((void**)&W1Th, g_W1Th); cudaGetSymbolAddress((void**)&W1Tl, g_W1Tl);
    cudaGetSymbolAddress((void**)&W2Th, g_W2Th); cudaGetSymbolAddress((void**)&W2Tl, g_W2Tl);
    cudaGetSymbolAddress((void**)&AQh, g_AQh); cudaGetSymbolAddress((void**)&AQl, g_AQl);
    cudaGetSymbolAddress((void**)&AKh, g_AKh); cudaGetSymbolAddress((void**)&AKl, g_AKl);
    cudaGetSymbolAddress((void**)&AVh, g_AVh); cudaGetSymbolAddress((void**)&AVl, g_AVl);
    cudaGetSymbolAddress((void**)&Qhp, g_Qh); cudaGetSymbolAddress((void**)&Qlp, g_Ql);
    cudaGetSymbolAddress((void**)&Khp, g_Kh); cudaGetSymbolAddress((void**)&Klp, g_Kl);
    cudaGetSymbolAddress((void**)&Vfp, g_Vf);
    cudaGetSymbolAddress((void**)&Vhp, g_Vh); cudaGetSymbolAddress((void**)&Vlp, g_Vl);
    cudaGetSymbolAddress((void**)&Ohp, g_Oh); cudaGetSymbolAddress((void**)&Olp, g_Ol);
    cudaGetSymbolAddress((void**)&Tp, g_T); cudaGetSymbolAddress((void**)&Rp, g_R);
    cudaGetSymbolAddress((void**)&Rhp, g_Rh); cudaGetSymbolAddress((void**)&Rlp, g_Rl);
    cudaGetSymbolAddress((void**)&Hhp, g_Hh); cudaGetSymbolAddress((void**)&Hlp, g_Hl);

    cudaFuncSetAttribute(gemm_split<0>, cudaFuncAttributeMaxDynamicSharedMemorySize, 3*G_STAGE);
    cudaFuncSetAttribute(gemm_split<1>, cudaFuncAttributeMaxDynamicSharedMemorySize, 3*G_STAGE);
    cudaFuncSetAttribute(gemm_split<2>, cudaFuncAttributeMaxDynamicSharedMemorySize, 3*G_STAGE);
    cudaFuncSetAttribute(attn_mma, cudaFuncAttributeMaxDynamicSharedMemorySize, A_SMEM);

    dim3 tb(32, 8);

    // 0..4 — ordered so the first GEMM lands at launch index 5 (ncu -s 5)
    split_plain<<<4096, 256>>>(query, AQh, AQl, MTOT*1024/4);          // 0
    transpose_split<<<dim3(32,32), tb>>>(Wq, WqTh, WqTl, 1024, 1024);  // 1
    split_plain<<<4096, 256>>>(key_,  AKh, AKl, MTOT*1024/4);          // 2
    transpose_split<<<dim3(32,32), tb>>>(Wk, WkTh, WkTl, 1024, 1024);  // 3
    split_plain<<<4096, 256>>>(value, AVh, AVl, MTOT*1024/4);          // 4

    // 5 — Q projection (profiled): scaled split direct to head layout
    gemm_split<1><<<dim3(8,32), 256, 3*G_STAGE>>>(AQh, AQl, WqTh, WqTl, bq,
        nullptr, Qhp, Qlp, 0.03125f, MTOT, 1024, 1024);

    transpose_split<<<dim3(32,32), tb>>>(Wv, WvTh, WvTl, 1024, 1024);  // 6
    gemm_split<1><<<dim3(8,32), 256, 3*G_STAGE>>>(AKh, AKl, WkTh, WkTl, bk,
        nullptr, Khp, Klp, 1.0f, MTOT, 1024, 1024);                    // 7
    gemm_split<0><<<dim3(8,32), 256, 3*G_STAGE>>>(AVh, AVl, WvTh, WvTl, bv,
        Vfp, nullptr, nullptr, 1.0f, MTOT, 1024, 1024);                // 8

    transpose_split<<<dim3(32,32), tb>>>(Wc, WcTh, WcTl, 1024, 1024);  // 9
    transpose_split<<<dim3(16,32), tb>>>(w1, W1Th, W1Tl, 1024, 512);   // 10
    transpose_split<<<dim3(32,16), tb>>>(w2, W2Th, W2Tl, 512, 1024);   // 11

    v_transpose_split<<<dim3(64, 2, 32), tb>>>(Vfp, Vhp, Vlp);         // 12

    // Attention -> split bf16 O
    attn_mma<<<dim3(SS/64, HH, BB), 128, A_SMEM>>>(Qhp, Qlp, Khp, Klp,
        Vhp, Vlp, mask, Ohp, Olp);                                     // 13

    // Output projection
    gemm_split<0><<<dim3(8,32), 256, 3*G_STAGE>>>(Ohp, Olp, WcTh, WcTl, bc,
        Tp, nullptr, nullptr, 1.0f, MTOT, 1024, 1024);                 // 14

    // RMSNorm 1 (emit fp32 + split)
    add_rmsnorm<1><<<MTOT, 256>>>(Tp, query, rms1, Rp, Rhp, Rlp);      // 15

    // MLP
    gemm_split<2><<<dim3(4,32), 256, 3*G_STAGE>>>(Rhp, Rlp, W1Th, W1Tl, b1,
        nullptr, Hhp, Hlp, 1.0f, MTOT, 512, 1024);                     // 16
    gemm_split<0><<<dim3(8,32), 256, 3*G_STAGE>>>(Hhp, Hlp, W2Th, W2Tl, b2,
        Tp, nullptr, nullptr, 1.0f, MTOT, 1024, 512);                  // 17

    // RMSNorm 2 -> output
    add_rmsnorm<0><<<MTOT, 256>>>(Rp, Tp, rms2, out, nullptr, nullptr); // 18
}